// round 3
// baseline (speedup 1.0000x reference)
#include <cuda_runtime.h>
#include <math.h>

#define NTH 256
#define RPB 8

// ---------------- transposed weight scratch (device globals, no allocs) ----
__device__ float g_WhhT[256*768];    // [i*768+o]
__device__ float g_WihT[8*768];      // [ii*768+o]
__device__ float g_e1T [256*256];    // [i*256+o]
__device__ float g_e2T [256*512];    // [i*512+oo]
__device__ float g_oWT [4][256*256]; // [l][i*256+o]

__global__ void prep_kernel(const float* __restrict__ Wih, const float* __restrict__ Whh,
                            const float* __restrict__ eW1, const float* __restrict__ eW2,
                            const float* __restrict__ oW1, const float* __restrict__ oW2,
                            const float* __restrict__ oW3, const float* __restrict__ oW4)
{
    for (int idx = blockIdx.x*blockDim.x + threadIdx.x; idx < 196608;
         idx += gridDim.x*blockDim.x) {
        { int o = idx/256, i = idx%256; g_WhhT[i*768+o] = Whh[idx]; }
        if (idx < 6144)  { int o = idx/8,  ii = idx%8;  g_WihT[ii*768+o] = Wih[idx]; }
        if (idx < 65536) {
            int o = idx/256, i = idx%256;
            g_e1T[i*256+o]    = eW1[idx];
            g_oWT[0][i*256+o] = oW1[idx];
            g_oWT[1][i*256+o] = oW2[idx];
            g_oWT[2][i*256+o] = oW3[idx];
            g_oWT[3][i*256+o] = oW4[idx];
        }
        if (idx < 131072){ int oo = idx/256, i = idx%256; g_e2T[i*512+oo] = eW2[idx]; }
    }
}

// ---------------- helpers ----------------
__device__ __forceinline__ float selu_f(float x){
    const float sc = 1.0507009873554805f, al = 1.6732632423543772f;
    return x > 0.f ? sc*x : sc*(al*expm1f(x));
}
__device__ __forceinline__ float sigmoid_f(float x){ return 1.f/(1.f+expf(-x)); }

#define FMA8(A,W,P,Q) do{ \
  A[0]=fmaf((P).x,(W),A[0]); A[1]=fmaf((P).y,(W),A[1]); A[2]=fmaf((P).z,(W),A[2]); A[3]=fmaf((P).w,(W),A[3]); \
  A[4]=fmaf((Q).x,(W),A[4]); A[5]=fmaf((Q).y,(W),A[5]); A[6]=fmaf((Q).z,(W),A[6]); A[7]=fmaf((Q).w,(W),A[7]); }while(0)

// outT[o*8+r] = act(bias[o] + sum_i inT[i*8+r]*WT[i*256+o]);  NO trailing sync.
template<int ACT>
__device__ __forceinline__ void matvec256(const float* __restrict__ WT,
                                          const float* __restrict__ bias,
                                          const float* __restrict__ inT,
                                          float* __restrict__ outT)
{
    const int o = threadIdx.x;
    float b = bias[o];
    float acc[8];
#pragma unroll
    for (int r = 0; r < 8; r++) acc[r] = b;
    const float4* in4 = (const float4*)inT;
    const float* wp = WT + o;
#pragma unroll 4
    for (int i = 0; i < 256; i++) {
        float  w = __ldg(wp + i*256);
        float4 p = in4[2*i], q = in4[2*i+1];
        FMA8(acc, w, p, q);
    }
#pragma unroll
    for (int r = 0; r < 8; r++) {
        float v = acc[r];
        if (ACT == 1) v = selu_f(v);
        else if (ACT == 2) v = fmaxf(v, 0.f);
        outT[o*8 + r] = v;
    }
}

__device__ __forceinline__ void feval(const float* __restrict__ inT, float* __restrict__ outT,
                                      float* __restrict__ aT, float* __restrict__ bT,
                                      const float* ob1, const float* ob2,
                                      const float* ob3, const float* ob4)
{
    matvec256<1>(g_oWT[0], ob1, inT, aT);  __syncthreads();
    matvec256<1>(g_oWT[1], ob2, aT,  bT);  __syncthreads();
    matvec256<1>(g_oWT[2], ob3, bT,  aT);  __syncthreads();
    matvec256<0>(g_oWT[3], ob4, aT, outT); __syncthreads();
}

// ---------------- main persistent kernel ----------------
__global__ __launch_bounds__(NTH, 1)
void node_kernel(const float* __restrict__ x,     const float* __restrict__ meta,
                 const float* __restrict__ eps,   const float* __restrict__ times,
                 const float* __restrict__ doses,
                 const float* __restrict__ gbih,  const float* __restrict__ gbhh,
                 const float* __restrict__ eb1,   const float* __restrict__ eb2,
                 const float* __restrict__ ob1,   const float* __restrict__ ob2,
                 const float* __restrict__ ob3,   const float* __restrict__ ob4,
                 const float* __restrict__ fcW,   const float* __restrict__ fcb,
                 float* __restrict__ out)
{
    extern __shared__ float sm[];
    float* yT   = sm + 0*2048;
    float* tmpT = sm + 1*2048;   // stage input / k7
    float* aT   = sm + 2*2048;   // scratch; reused as reduction buffer "red"
    float* bT   = sm + 3*2048;
    float* y5T  = sm + 4*2048;
    float* k1T  = sm + 5*2048;   // reused as x cache during GRU
    float* k2T  = sm + 6*2048;
    float* k3T  = sm + 7*2048;
    float* k4T  = sm + 8*2048;
    float* k5T  = sm + 9*2048;
    float* k6T  = sm +10*2048;
    float* red  = aT;
    float* xc   = k1T;

    __shared__ float t_s[8], t1_s[8], dt_s[8], d_s[8], ds_s[8], meta_s[32];
    __shared__ int   act_s[8], accfl[8];

    const int tid = threadIdx.x;
    const int o   = tid;
    const int r0  = blockIdx.x * RPB;

    // ---- caches ----
    for (int e = tid; e < 2048; e += NTH) { xc[e] = x[r0*256 + e]; yT[e] = 0.f; }
    if (tid < 32) meta_s[tid] = meta[r0*4 + tid];

    // GRU input-weight slice in registers (8 in-dims per gate)
    float wr[8], wz[8], wn[8];
#pragma unroll
    for (int ii = 0; ii < 8; ii++) {
        wr[ii] = g_WihT[ii*768 + o];
        wz[ii] = g_WihT[ii*768 + o + 256];
        wn[ii] = g_WihT[ii*768 + o + 512];
    }
    const float bir = gbih[o], biz = gbih[o+256], bin_ = gbih[o+512];
    const float bhr = gbhh[o], bhz = gbhh[o+256], bhn  = gbhh[o+512];
    __syncthreads();

    // ---------------- Phase A: GRU over 64 timesteps ----------------
    for (int t = 0; t < 64; t++) {
        float ar[8], az[8], an[8];
#pragma unroll
        for (int r = 0; r < 8; r++) { ar[r] = bhr; az[r] = bhz; an[r] = bhn; }
        const float4* h4 = (const float4*)yT;
        const float* w1p = g_WhhT + o;
        const float* w2p = g_WhhT + o + 256;
        const float* w3p = g_WhhT + o + 512;
#pragma unroll 2
        for (int i = 0; i < 256; i++) {
            float wa = __ldg(w1p + i*768), wb = __ldg(w2p + i*768), wc = __ldg(w3p + i*768);
            float4 p = h4[2*i], q = h4[2*i+1];
            FMA8(ar, wa, p, q);
            FMA8(az, wb, p, q);
            FMA8(an, wc, p, q);
        }
        float hnew[8];
#pragma unroll
        for (int r = 0; r < 8; r++) {
            float gr = bir, gz = biz, gn = bin_;
#pragma unroll
            for (int c = 0; c < 4; c++) {
                float xv = xc[r*256 + t*4 + c];
                gr = fmaf(xv, wr[c], gr); gz = fmaf(xv, wz[c], gz); gn = fmaf(xv, wn[c], gn);
            }
#pragma unroll
            for (int c = 0; c < 4; c++) {
                float mv = meta_s[r*4 + c];
                gr = fmaf(mv, wr[4+c], gr); gz = fmaf(mv, wz[4+c], gz); gn = fmaf(mv, wn[4+c], gn);
            }
            float rg = sigmoid_f(gr + ar[r]);
            float zg = sigmoid_f(gz + az[r]);
            float nn = tanhf(gn + rg*an[r]);
            float ho = yT[o*8 + r];
            hnew[r] = (1.f - zg)*nn + zg*ho;
        }
        __syncthreads();
#pragma unroll
        for (int r = 0; r < 8; r++) yT[o*8 + r] = hnew[r];
        __syncthreads();
    }

    // ---------------- Phase B: encoder -> y0 ----------------
    matvec256<2>(g_e1T, eb1, yT, aT);
    __syncthreads();
    {
        float am[8], as[8];
        float bm = eb2[o], bs = eb2[o + 256];
#pragma unroll
        for (int r = 0; r < 8; r++) { am[r] = bm; as[r] = bs; }
        const float4* a4 = (const float4*)aT;
        const float* wmp = g_e2T + o;
        const float* wsp = g_e2T + o + 256;
#pragma unroll 2
        for (int i = 0; i < 256; i++) {
            float wm = __ldg(wmp + i*512), ws = __ldg(wsp + i*512);
            float4 p = a4[2*i], q = a4[2*i+1];
            FMA8(am, wm, p, q);
            FMA8(as, ws, p, q);
        }
#pragma unroll
        for (int r = 0; r < 8; r++) {
            float ev = eps[(r0 + r)*256 + o];
            yT[o*8 + r] = fmaf(ev, as[r], am[r]);   // eps*std + mean
        }
        __syncthreads();
    }

    // ---------------- Phase C: 4 x dopri5 ----------------
    const float A21 = 0.2f;
    const float A31 = (float)(3.0/40.0),  A32 = (float)(9.0/40.0);
    const float A41 = (float)(44.0/45.0), A42 = (float)(-56.0/15.0), A43 = (float)(32.0/9.0);
    const float A51 = (float)(19372.0/6561.0), A52 = (float)(-25360.0/2187.0),
                A53 = (float)(64448.0/6561.0), A54 = (float)(-212.0/729.0);
    const float A61 = (float)(9017.0/3168.0), A62 = (float)(-355.0/33.0),
                A63 = (float)(46732.0/5247.0), A64 = (float)(49.0/176.0),
                A65 = (float)(-5103.0/18656.0);
    const float BC0 = (float)(35.0/384.0), BC2 = (float)(500.0/1113.0),
                BC3 = (float)(125.0/192.0), BC4 = (float)(-2187.0/6784.0),
                BC5 = (float)(11.0/84.0);
    const float EC0 = (float)(35.0/384.0 - 5179.0/57600.0);
    const float EC2 = (float)(500.0/1113.0 - 7571.0/16695.0);
    const float EC3 = (float)(125.0/192.0 - 393.0/640.0);
    const float EC4 = (float)(-2187.0/6784.0 + 92097.0/339200.0);
    const float EC5 = (float)(11.0/84.0 - 187.0/2100.0);
    const float EC6 = (float)(-1.0/40.0);

    for (int j = 0; j < 4; j++) {
        if (tid < 8) {
            int row = r0 + tid;
            float t0v = times[(j*1024 + row)*2 + 0];
            float t1v = times[(j*1024 + row)*2 + 1];
            t_s[tid]  = t0v;
            t1_s[tid] = t1v;
            dt_s[tid] = fmaxf(t1v - t0v, 1e-6f) * 0.1f;
            ds_s[tid] = (t0v < t1v) ? doses[j*1024 + row] : 0.f;
        }
        __syncthreads();
#pragma unroll
        for (int r = 0; r < 8; r++) yT[o*8 + r] += ds_s[r];

        for (int step = 0; step < 32; step++) {
            int myact = 0;
            if (tid < 8) {
                float tt = t_s[tid], t1v = t1_s[tid];
                myact = (tt < t1v) ? 1 : 0;
                act_s[tid] = myact;
                float rem = fmaxf(t1v - tt, 0.f);
                d_s[tid] = fminf(fmaxf(dt_s[tid], 0.f), rem);
            }
            if (!__syncthreads_or(myact)) break;   // uniform

            feval(yT, k1T, aT, bT, ob1, ob2, ob3, ob4);
#pragma unroll
            for (int r = 0; r < 8; r++) { int e = o*8+r;
                tmpT[e] = fmaf(d_s[r], A21*k1T[e], yT[e]); }
            __syncthreads();
            feval(tmpT, k2T, aT, bT, ob1, ob2, ob3, ob4);
#pragma unroll
            for (int r = 0; r < 8; r++) { int e = o*8+r;
                tmpT[e] = fmaf(d_s[r], A31*k1T[e] + A32*k2T[e], yT[e]); }
            __syncthreads();
            feval(tmpT, k3T, aT, bT, ob1, ob2, ob3, ob4);
#pragma unroll
            for (int r = 0; r < 8; r++) { int e = o*8+r;
                tmpT[e] = fmaf(d_s[r], A41*k1T[e] + A42*k2T[e] + A43*k3T[e], yT[e]); }
            __syncthreads();
            feval(tmpT, k4T, aT, bT, ob1, ob2, ob3, ob4);
#pragma unroll
            for (int r = 0; r < 8; r++) { int e = o*8+r;
                tmpT[e] = fmaf(d_s[r], A51*k1T[e] + A52*k2T[e] + A53*k3T[e] + A54*k4T[e], yT[e]); }
            __syncthreads();
            feval(tmpT, k5T, aT, bT, ob1, ob2, ob3, ob4);
#pragma unroll
            for (int r = 0; r < 8; r++) { int e = o*8+r;
                tmpT[e] = fmaf(d_s[r], A61*k1T[e] + A62*k2T[e] + A63*k3T[e] + A64*k4T[e] + A65*k5T[e], yT[e]); }
            __syncthreads();
            feval(tmpT, k6T, aT, bT, ob1, ob2, ob3, ob4);
#pragma unroll
            for (int r = 0; r < 8; r++) { int e = o*8+r;
                y5T[e] = fmaf(d_s[r], BC0*k1T[e] + BC2*k3T[e] + BC3*k4T[e] + BC4*k5T[e] + BC5*k6T[e], yT[e]); }
            __syncthreads();
            feval(y5T, tmpT, aT, bT, ob1, ob2, ob3, ob4);   // k7 in tmpT

            // error norm
#pragma unroll
            for (int r = 0; r < 8; r++) {
                int e = o*8+r;
                float err = d_s[r]*(EC0*k1T[e] + EC2*k3T[e] + EC3*k4T[e]
                                  + EC4*k5T[e] + EC5*k6T[e] + EC6*tmpT[e]);
                float sc = 1e-6f + 1e-3f*fmaxf(fabsf(yT[e]), fabsf(y5T[e]));
                float q = err/sc;
                red[r*256 + o] = q*q;
            }
            __syncthreads();
            if (tid < 8) {
                float s = 0.f;
                for (int i = 0; i < 256; i++) s += red[tid*256 + i];
                float en = sqrtf(s * (1.f/256.f));
                int active = act_s[tid];
                int acc = (en <= 1.f) && active;
                accfl[tid] = acc;
                float dtc = d_s[tid];
                if (acc) t_s[tid] += dtc;
                if (active) {
                    float fac = 0.9f * powf(en + 1e-10f, -0.2f);
                    fac = fminf(fmaxf(fac, 0.2f), 10.f);
                    dt_s[tid] = fmaxf(dtc, 1e-8f) * fac;
                }
            }
            __syncthreads();
#pragma unroll
            for (int r = 0; r < 8; r++) if (accfl[r]) { int e = o*8+r; yT[e] = y5T[e]; }
            __syncthreads();
        }
    }

    // ---------------- Phase D: linear head ----------------
    {
        float fcw = fcW[o];
#pragma unroll
        for (int r = 0; r < 8; r++) red[r*256 + o] = yT[o*8 + r] * fcw;
        __syncthreads();
        if (tid < 8) {
            float s = fcb[0];
            for (int i = 0; i < 256; i++) s += red[tid*256 + i];
#pragma unroll
            for (int c = 0; c < 4; c++) s += meta_s[tid*4 + c] * fcW[256 + c];
            out[r0 + tid] = s;
        }
    }
}

extern "C" void kernel_launch(void* const* d_in, const int* in_sizes, int n_in,
                              void* d_out, int out_size)
{
    const float* x     = (const float*)d_in[0];
    const float* meta  = (const float*)d_in[1];
    const float* eps   = (const float*)d_in[2];
    const float* times = (const float*)d_in[3];
    const float* doses = (const float*)d_in[4];
    const float* gWih  = (const float*)d_in[5];
    const float* gWhh  = (const float*)d_in[6];
    const float* gbih  = (const float*)d_in[7];
    const float* gbhh  = (const float*)d_in[8];
    const float* eW1   = (const float*)d_in[9];
    const float* eb1   = (const float*)d_in[10];
    const float* eW2   = (const float*)d_in[11];
    const float* eb2   = (const float*)d_in[12];
    const float* oW1   = (const float*)d_in[13];
    const float* ob1   = (const float*)d_in[14];
    const float* oW2   = (const float*)d_in[15];
    const float* ob2   = (const float*)d_in[16];
    const float* oW3   = (const float*)d_in[17];
    const float* ob3   = (const float*)d_in[18];
    const float* oW4   = (const float*)d_in[19];
    const float* ob4   = (const float*)d_in[20];
    const float* fcW   = (const float*)d_in[21];
    const float* fcb   = (const float*)d_in[22];
    float* out = (float*)d_out;

    prep_kernel<<<768, 256>>>(gWih, gWhh, eW1, eW2, oW1, oW2, oW3, oW4);

    const int smem_bytes = 11 * 2048 * sizeof(float);   // 90112
    static int attr_done = 0;
    if (!attr_done) {
        cudaFuncSetAttribute(node_kernel, cudaFuncAttributeMaxDynamicSharedMemorySize, smem_bytes);
        attr_done = 1;
    }
    node_kernel<<<128, NTH, smem_bytes>>>(x, meta, eps, times, doses,
                                          gbih, gbhh, eb1, eb2,
                                          ob1, ob2, ob3, ob4, fcW, fcb, out);
}

// round 5
// speedup vs baseline: 1.6504x; 1.6504x over previous
#include <cuda_runtime.h>
#include <math.h>

#define NTH 512
#define RPB 8

typedef unsigned long long ull;

// ---------------- transposed weight scratch (device globals, no allocs) ----
__device__ float g_WhhT[256*768];    // [i*768+o]
__device__ float g_WihT[8*768];      // [ii*768+o]
__device__ float g_e1T [256*256];    // [i*256+o]
__device__ float g_e2T [256*512];    // [i*512+oo]
__device__ float g_oWT [4][256*256]; // [l][i*256+o]

__global__ void prep_kernel(const float* __restrict__ Wih, const float* __restrict__ Whh,
                            const float* __restrict__ eW1, const float* __restrict__ eW2,
                            const float* __restrict__ oW1, const float* __restrict__ oW2,
                            const float* __restrict__ oW3, const float* __restrict__ oW4)
{
    for (int idx = blockIdx.x*blockDim.x + threadIdx.x; idx < 196608;
         idx += gridDim.x*blockDim.x) {
        { int o = idx/256, i = idx%256; g_WhhT[i*768+o] = Whh[idx]; }
        if (idx < 6144)  { int o = idx/8,  ii = idx%8;  g_WihT[ii*768+o] = Wih[idx]; }
        if (idx < 65536) {
            int o = idx/256, i = idx%256;
            g_e1T[i*256+o]    = eW1[idx];
            g_oWT[0][i*256+o] = oW1[idx];
            g_oWT[1][i*256+o] = oW2[idx];
            g_oWT[2][i*256+o] = oW3[idx];
            g_oWT[3][i*256+o] = oW4[idx];
        }
        if (idx < 131072){ int oo = idx/256, i = idx%256; g_e2T[i*512+oo] = eW2[idx]; }
    }
}

// ---------------- f32x2 helpers ----------------
__device__ __forceinline__ ull pack2(float a, float b){
    ull r; asm("mov.b64 %0, {%1, %2};" : "=l"(r) : "f"(a), "f"(b)); return r;
}
__device__ __forceinline__ void unpack2(ull v, float& a, float& b){
    asm("mov.b64 {%0, %1}, %2;" : "=f"(a), "=f"(b) : "l"(v));
}
__device__ __forceinline__ void fma2(ull& acc, ull a, ull b){
    asm("fma.rn.f32x2 %0, %1, %2, %0;" : "+l"(acc) : "l"(a), "l"(b));
}

__device__ __forceinline__ float selu_f(float x){
    const float sc = 1.0507009873554805f, al = 1.6732632423543772f;
    return x > 0.f ? sc*x : sc*(al*expm1f(x));
}
__device__ __forceinline__ float sigmoid_f(float x){ return 1.f/(1.f+expf(-x)); }

// Activation layout: element (row r, col c) at buf[(r>>2)*1024 + c*4 + (r&3)]
// matvec: outT[h][o] (4 rows) = act(bias[o] + sum_i inT[h][i]*WT[i*256+o])
template<int ACT>
__device__ __forceinline__ void matvec256(const float* __restrict__ WT,
                                          const float* __restrict__ bias,
                                          const float* __restrict__ inT,
                                          float* __restrict__ outT,
                                          int o, int h)
{
    float b = bias[o];
    ull acc0 = pack2(b, b), acc1 = pack2(b, b);
    const float4* in4 = (const float4*)(inT + h*1024);
    const float* wp = WT + o;
#pragma unroll 8
    for (int i = 0; i < 256; i++) {
        float w = __ldg(wp + i*256);
        ull w2 = pack2(w, w);
        float4 u = in4[i];
        fma2(acc0, pack2(u.x, u.y), w2);
        fma2(acc1, pack2(u.z, u.w), w2);
    }
    float v0,v1,v2,v3;
    unpack2(acc0, v0, v1); unpack2(acc1, v2, v3);
    if (ACT == 1) { v0=selu_f(v0); v1=selu_f(v1); v2=selu_f(v2); v3=selu_f(v3); }
    else if (ACT == 2) { v0=fmaxf(v0,0.f); v1=fmaxf(v1,0.f); v2=fmaxf(v2,0.f); v3=fmaxf(v3,0.f); }
    *(float4*)(outT + h*1024 + o*4) = make_float4(v0, v1, v2, v3);
}

__device__ __forceinline__ void feval(const float* __restrict__ inT, float* __restrict__ outT,
                                      float* __restrict__ aT, float* __restrict__ bT,
                                      const float* ob1, const float* ob2,
                                      const float* ob3, const float* ob4, int o, int h)
{
    matvec256<1>(g_oWT[0], ob1, inT, aT, o, h);  __syncthreads();
    matvec256<1>(g_oWT[1], ob2, aT,  bT, o, h);  __syncthreads();
    matvec256<1>(g_oWT[2], ob3, bT,  aT, o, h);  __syncthreads();
    matvec256<0>(g_oWT[3], ob4, aT, outT, o, h); __syncthreads();
}

// ---------------- main persistent kernel ----------------
__global__ __launch_bounds__(NTH, 1)
void node_kernel(const float* __restrict__ x,     const float* __restrict__ meta,
                 const float* __restrict__ eps,   const float* __restrict__ times,
                 const float* __restrict__ doses,
                 const float* __restrict__ gbih,  const float* __restrict__ gbhh,
                 const float* __restrict__ eb1,   const float* __restrict__ eb2,
                 const float* __restrict__ ob1,   const float* __restrict__ ob2,
                 const float* __restrict__ ob3,   const float* __restrict__ ob4,
                 const float* __restrict__ fcW,   const float* __restrict__ fcb,
                 float* __restrict__ out)
{
    extern __shared__ float sm[];
    float* yT   = sm + 0*2048;
    float* tmpT = sm + 1*2048;   // stage input / k7
    float* aT   = sm + 2*2048;   // scratch; reused as reduction buffer
    float* bT   = sm + 3*2048;
    float* y5T  = sm + 4*2048;
    float* k1T  = sm + 5*2048;   // reused as x cache during GRU
    float* k2T  = sm + 6*2048;
    float* k3T  = sm + 7*2048;
    float* k4T  = sm + 8*2048;
    float* k5T  = sm + 9*2048;
    float* k6T  = sm +10*2048;
    float* red  = aT;
    float* xc   = k1T;

    __shared__ float t_s[8], t1_s[8], dt_s[8], d_s[8], ds_s[8], meta_s[32];
    __shared__ int   act_s[8], accfl[8];

    const int tid  = threadIdx.x;
    const int o    = tid & 255;
    const int h    = tid >> 8;
    const int wid  = tid >> 5;
    const int lane = tid & 31;
    const int r0   = blockIdx.x * RPB;
    const int base = h*1024 + o*4;   // my 4 contiguous elements (rows 4h..4h+3, col o)

    // ---- caches ----
    for (int e = tid; e < 2048; e += NTH) { xc[e] = x[r0*256 + e]; yT[e] = 0.f; }
    if (tid < 32) meta_s[tid] = meta[r0*4 + tid];

    // GRU input-weight slice in registers (8 in-dims per gate) — per (o) column
    float wr[8], wz[8], wn[8];
#pragma unroll
    for (int ii = 0; ii < 8; ii++) {
        wr[ii] = g_WihT[ii*768 + o];
        wz[ii] = g_WihT[ii*768 + o + 256];
        wn[ii] = g_WihT[ii*768 + o + 512];
    }
    const float bir = gbih[o], biz = gbih[o+256], bin_ = gbih[o+512];
    const float bhr = gbhh[o], bhz = gbhh[o+256], bhn  = gbhh[o+512];
    __syncthreads();

    // ---------------- Phase A: GRU over 64 timesteps ----------------
    for (int t = 0; t < 64; t++) {
        ull ar0 = pack2(bhr,bhr), ar1 = pack2(bhr,bhr);
        ull az0 = pack2(bhz,bhz), az1 = pack2(bhz,bhz);
        ull an0 = pack2(bhn,bhn), an1 = pack2(bhn,bhn);
        const float4* h4 = (const float4*)(yT + h*1024);
        const float* w1p = g_WhhT + o;
        const float* w2p = g_WhhT + o + 256;
        const float* w3p = g_WhhT + o + 512;
#pragma unroll 4
        for (int i = 0; i < 256; i++) {
            float wa = __ldg(w1p + i*768), wb = __ldg(w2p + i*768), wc = __ldg(w3p + i*768);
            float4 p = h4[i];
            ull p01 = pack2(p.x, p.y), p23 = pack2(p.z, p.w);
            ull wa2 = pack2(wa, wa), wb2 = pack2(wb, wb), wc2 = pack2(wc, wc);
            fma2(ar0, p01, wa2); fma2(ar1, p23, wa2);
            fma2(az0, p01, wb2); fma2(az1, p23, wb2);
            fma2(an0, p01, wc2); fma2(an1, p23, wc2);
        }
        float arr[4], azr[4], anr[4];
        unpack2(ar0, arr[0], arr[1]); unpack2(ar1, arr[2], arr[3]);
        unpack2(az0, azr[0], azr[1]); unpack2(az1, azr[2], azr[3]);
        unpack2(an0, anr[0], anr[1]); unpack2(an1, anr[2], anr[3]);
        float hnew[4];
#pragma unroll
        for (int k = 0; k < 4; k++) {
            int r = 4*h + k;
            float gr = bir, gz = biz, gn = bin_;
#pragma unroll
            for (int c = 0; c < 4; c++) {
                float xv = xc[r*256 + t*4 + c];
                gr = fmaf(xv, wr[c], gr); gz = fmaf(xv, wz[c], gz); gn = fmaf(xv, wn[c], gn);
            }
#pragma unroll
            for (int c = 0; c < 4; c++) {
                float mv = meta_s[r*4 + c];
                gr = fmaf(mv, wr[4+c], gr); gz = fmaf(mv, wz[4+c], gz); gn = fmaf(mv, wn[4+c], gn);
            }
            float rg = sigmoid_f(gr + arr[k]);
            float zg = sigmoid_f(gz + azr[k]);
            float nn = tanhf(gn + rg*anr[k]);
            float ho = yT[base + k];
            hnew[k] = (1.f - zg)*nn + zg*ho;
        }
        __syncthreads();
        *(float4*)(yT + base) = make_float4(hnew[0], hnew[1], hnew[2], hnew[3]);
        __syncthreads();
    }

    // ---------------- Phase B: encoder -> y0 ----------------
    matvec256<2>(g_e1T, eb1, yT, bT, o, h);   // relu layer into bT (keep yT = h for now)
    __syncthreads();
    {
        float bm = eb2[o], bs = eb2[o + 256];
        ull am0 = pack2(bm,bm), am1 = pack2(bm,bm);
        ull as0 = pack2(bs,bs), as1 = pack2(bs,bs);
        const float4* a4 = (const float4*)(bT + h*1024);
        const float* wmp = g_e2T + o;
        const float* wsp = g_e2T + o + 256;
#pragma unroll 4
        for (int i = 0; i < 256; i++) {
            float wm = __ldg(wmp + i*512), ws = __ldg(wsp + i*512);
            float4 p = a4[i];
            ull p01 = pack2(p.x, p.y), p23 = pack2(p.z, p.w);
            ull wm2 = pack2(wm, wm), ws2 = pack2(ws, ws);
            fma2(am0, p01, wm2); fma2(am1, p23, wm2);
            fma2(as0, p01, ws2); fma2(as1, p23, ws2);
        }
        float mm[4], ss[4];
        unpack2(am0, mm[0], mm[1]); unpack2(am1, mm[2], mm[3]);
        unpack2(as0, ss[0], ss[1]); unpack2(as1, ss[2], ss[3]);
        __syncthreads();
        float4 y0;
        y0.x = fmaf(eps[(r0 + 4*h + 0)*256 + o], ss[0], mm[0]);
        y0.y = fmaf(eps[(r0 + 4*h + 1)*256 + o], ss[1], mm[1]);
        y0.z = fmaf(eps[(r0 + 4*h + 2)*256 + o], ss[2], mm[2]);
        y0.w = fmaf(eps[(r0 + 4*h + 3)*256 + o], ss[3], mm[3]);
        *(float4*)(yT + base) = y0;
        __syncthreads();
    }

    // ---------------- Phase C: 4 x dopri5 ----------------
    const float A21 = 0.2f;
    const float A31 = (float)(3.0/40.0),  A32 = (float)(9.0/40.0);
    const float A41 = (float)(44.0/45.0), A42 = (float)(-56.0/15.0), A43 = (float)(32.0/9.0);
    const float A51 = (float)(19372.0/6561.0), A52 = (float)(-25360.0/2187.0),
                A53 = (float)(64448.0/6561.0), A54 = (float)(-212.0/729.0);
    const float A61 = (float)(9017.0/3168.0), A62 = (float)(-355.0/33.0),
                A63 = (float)(46732.0/5247.0), A64 = (float)(49.0/176.0),
                A65 = (float)(-5103.0/18656.0);
    const float BC0 = (float)(35.0/384.0), BC2 = (float)(500.0/1113.0),
                BC3 = (float)(125.0/192.0), BC4 = (float)(-2187.0/6784.0),
                BC5 = (float)(11.0/84.0);
    const float EC0 = (float)(35.0/384.0 - 5179.0/57600.0);
    const float EC2 = (float)(500.0/1113.0 - 7571.0/16695.0);
    const float EC3 = (float)(125.0/192.0 - 393.0/640.0);
    const float EC4 = (float)(-2187.0/6784.0 + 92097.0/339200.0);
    const float EC5 = (float)(11.0/84.0 - 187.0/2100.0);
    const float EC6 = (float)(-1.0/40.0);

    for (int j = 0; j < 4; j++) {
        if (tid < 8) {
            int row = r0 + tid;
            float t0v = times[(j*1024 + row)*2 + 0];
            float t1v = times[(j*1024 + row)*2 + 1];
            t_s[tid]  = t0v;
            t1_s[tid] = t1v;
            dt_s[tid] = fmaxf(t1v - t0v, 1e-6f) * 0.1f;
            ds_s[tid] = (t0v < t1v) ? doses[j*1024 + row] : 0.f;
        }
        __syncthreads();
        {
            float4 y = *(float4*)(yT + base);
            y.x += ds_s[4*h+0]; y.y += ds_s[4*h+1]; y.z += ds_s[4*h+2]; y.w += ds_s[4*h+3];
            *(float4*)(yT + base) = y;
        }

        for (int step = 0; step < 32; step++) {
            int myact = 0;
            if (tid < 8) {
                float tt = t_s[tid], t1v = t1_s[tid];
                myact = (tt < t1v) ? 1 : 0;
                act_s[tid] = myact;
                float rem = fmaxf(t1v - tt, 0.f);
                d_s[tid] = fminf(fmaxf(dt_s[tid], 0.f), rem);
            }
            if (!__syncthreads_or(myact)) break;   // uniform exit

            const float d0 = d_s[4*h+0], d1 = d_s[4*h+1], d2 = d_s[4*h+2], d3 = d_s[4*h+3];

#define COMB4(DST, EXPRX, EXPRY, EXPRZ, EXPRW) do { \
            float4 _y = *(float4*)(yT + base); \
            float4 _t; \
            _t.x = fmaf(d0, (EXPRX), _y.x); _t.y = fmaf(d1, (EXPRY), _y.y); \
            _t.z = fmaf(d2, (EXPRZ), _y.z); _t.w = fmaf(d3, (EXPRW), _y.w); \
            *(float4*)(DST + base) = _t; } while(0)

            feval(yT, k1T, aT, bT, ob1, ob2, ob3, ob4, o, h);
            {
                float4 a = *(float4*)(k1T + base);
                COMB4(tmpT, A21*a.x, A21*a.y, A21*a.z, A21*a.w);
            }
            __syncthreads();
            feval(tmpT, k2T, aT, bT, ob1, ob2, ob3, ob4, o, h);
            {
                float4 a = *(float4*)(k1T + base); float4 b = *(float4*)(k2T + base);
                COMB4(tmpT, A31*a.x + A32*b.x, A31*a.y + A32*b.y,
                            A31*a.z + A32*b.z, A31*a.w + A32*b.w);
            }
            __syncthreads();
            feval(tmpT, k3T, aT, bT, ob1, ob2, ob3, ob4, o, h);
            {
                float4 a = *(float4*)(k1T + base); float4 b = *(float4*)(k2T + base);
                float4 c = *(float4*)(k3T + base);
                COMB4(tmpT, A41*a.x + A42*b.x + A43*c.x, A41*a.y + A42*b.y + A43*c.y,
                            A41*a.z + A42*b.z + A43*c.z, A41*a.w + A42*b.w + A43*c.w);
            }
            __syncthreads();
            feval(tmpT, k4T, aT, bT, ob1, ob2, ob3, ob4, o, h);
            {
                float4 a = *(float4*)(k1T + base); float4 b = *(float4*)(k2T + base);
                float4 c = *(float4*)(k3T + base); float4 e = *(float4*)(k4T + base);
                COMB4(tmpT, A51*a.x + A52*b.x + A53*c.x + A54*e.x,
                            A51*a.y + A52*b.y + A53*c.y + A54*e.y,
                            A51*a.z + A52*b.z + A53*c.z + A54*e.z,
                            A51*a.w + A52*b.w + A53*c.w + A54*e.w);
            }
            __syncthreads();
            feval(tmpT, k5T, aT, bT, ob1, ob2, ob3, ob4, o, h);
            {
                float4 a = *(float4*)(k1T + base); float4 b = *(float4*)(k2T + base);
                float4 c = *(float4*)(k3T + base); float4 e = *(float4*)(k4T + base);
                float4 f = *(float4*)(k5T + base);
                COMB4(tmpT, A61*a.x + A62*b.x + A63*c.x + A64*e.x + A65*f.x,
                            A61*a.y + A62*b.y + A63*c.y + A64*e.y + A65*f.y,
                            A61*a.z + A62*b.z + A63*c.z + A64*e.z + A65*f.z,
                            A61*a.w + A62*b.w + A63*c.w + A64*e.w + A65*f.w);
            }
            __syncthreads();
            feval(tmpT, k6T, aT, bT, ob1, ob2, ob3, ob4, o, h);
            {
                float4 a = *(float4*)(k1T + base); float4 c = *(float4*)(k3T + base);
                float4 e = *(float4*)(k4T + base); float4 f = *(float4*)(k5T + base);
                float4 g = *(float4*)(k6T + base);
                COMB4(y5T, BC0*a.x + BC2*c.x + BC3*e.x + BC4*f.x + BC5*g.x,
                           BC0*a.y + BC2*c.y + BC3*e.y + BC4*f.y + BC5*g.y,
                           BC0*a.z + BC2*c.z + BC3*e.z + BC4*f.z + BC5*g.z,
                           BC0*a.w + BC2*c.w + BC3*e.w + BC4*f.w + BC5*g.w);
            }
            __syncthreads();
            feval(y5T, tmpT, aT, bT, ob1, ob2, ob3, ob4, o, h);   // k7 -> tmpT

            // error norm contributions -> red (== aT, free now)
            {
                float4 a = *(float4*)(k1T + base); float4 c = *(float4*)(k3T + base);
                float4 e = *(float4*)(k4T + base); float4 f = *(float4*)(k5T + base);
                float4 g = *(float4*)(k6T + base); float4 s7 = *(float4*)(tmpT + base);
                float4 y = *(float4*)(yT + base);  float4 y5 = *(float4*)(y5T + base);
                float q[4];
                float ex = EC0*a.x + EC2*c.x + EC3*e.x + EC4*f.x + EC5*g.x + EC6*s7.x;
                float ey = EC0*a.y + EC2*c.y + EC3*e.y + EC4*f.y + EC5*g.y + EC6*s7.y;
                float ez = EC0*a.z + EC2*c.z + EC3*e.z + EC4*f.z + EC5*g.z + EC6*s7.z;
                float ew = EC0*a.w + EC2*c.w + EC3*e.w + EC4*f.w + EC5*g.w + EC6*s7.w;
                q[0] = d0*ex / (1e-6f + 1e-3f*fmaxf(fabsf(y.x), fabsf(y5.x)));
                q[1] = d1*ey / (1e-6f + 1e-3f*fmaxf(fabsf(y.y), fabsf(y5.y)));
                q[2] = d2*ez / (1e-6f + 1e-3f*fmaxf(fabsf(y.z), fabsf(y5.z)));
                q[3] = d3*ew / (1e-6f + 1e-3f*fmaxf(fabsf(y.w), fabsf(y5.w)));
                *(float4*)(red + base) = make_float4(q[0]*q[0], q[1]*q[1], q[2]*q[2], q[3]*q[3]);
            }
            __syncthreads();
            // warp r (r<8) reduces row r
            if (wid < 8) {
                int r = wid;
                const float* rp = red + (r>>2)*1024 + (r&3);
                float s = 0.f;
#pragma unroll
                for (int c = 0; c < 8; c++) s += rp[(lane + 32*c)*4];
                s += __shfl_xor_sync(0xffffffffu, s, 16);
                s += __shfl_xor_sync(0xffffffffu, s, 8);
                s += __shfl_xor_sync(0xffffffffu, s, 4);
                s += __shfl_xor_sync(0xffffffffu, s, 2);
                s += __shfl_xor_sync(0xffffffffu, s, 1);
                if (lane == 0) {
                    float en = sqrtf(s * (1.f/256.f));
                    int active = act_s[r];
                    int acc = (en <= 1.f) && active;
                    accfl[r] = acc;
                    float dtc = d_s[r];
                    if (acc) t_s[r] += dtc;
                    if (active) {
                        float fac = 0.9f * powf(en + 1e-10f, -0.2f);
                        fac = fminf(fmaxf(fac, 0.2f), 10.f);
                        dt_s[r] = fmaxf(dtc, 1e-8f) * fac;
                    }
                }
            }
            __syncthreads();
            {
                float4 y = *(float4*)(yT + base);
                float4 y5 = *(float4*)(y5T + base);
                if (accfl[4*h+0]) y.x = y5.x;
                if (accfl[4*h+1]) y.y = y5.y;
                if (accfl[4*h+2]) y.z = y5.z;
                if (accfl[4*h+3]) y.w = y5.w;
                *(float4*)(yT + base) = y;
            }
            __syncthreads();
#undef COMB4
        }
    }

    // ---------------- Phase D: linear head ----------------
    {
        float fcw = fcW[o];
        float4 y = *(float4*)(yT + base);
        *(float4*)(red + base) = make_float4(y.x*fcw, y.y*fcw, y.z*fcw, y.w*fcw);
        __syncthreads();
        if (wid < 8) {
            int r = wid;
            const float* rp = red + (r>>2)*1024 + (r&3);
            float s = 0.f;
#pragma unroll
            for (int c = 0; c < 8; c++) s += rp[(lane + 32*c)*4];
            s += __shfl_xor_sync(0xffffffffu, s, 16);
            s += __shfl_xor_sync(0xffffffffu, s, 8);
            s += __shfl_xor_sync(0xffffffffu, s, 4);
            s += __shfl_xor_sync(0xffffffffu, s, 2);
            s += __shfl_xor_sync(0xffffffffu, s, 1);
            if (lane == 0) {
                s += fcb[0];
#pragma unroll
                for (int c = 0; c < 4; c++) s += meta_s[r*4 + c] * fcW[256 + c];
                out[r0 + r] = s;
            }
        }
    }
}

extern "C" void kernel_launch(void* const* d_in, const int* in_sizes, int n_in,
                              void* d_out, int out_size)
{
    const float* x     = (const float*)d_in[0];
    const float* meta  = (const float*)d_in[1];
    const float* eps   = (const float*)d_in[2];
    const float* times = (const float*)d_in[3];
    const float* doses = (const float*)d_in[4];
    const float* gWih  = (const float*)d_in[5];
    const float* gWhh  = (const float*)d_in[6];
    const float* gbih  = (const float*)d_in[7];
    const float* gbhh  = (const float*)d_in[8];
    const float* eW1   = (const float*)d_in[9];
    const float* eb1   = (const float*)d_in[10];
    const float* eW2   = (const float*)d_in[11];
    const float* eb2   = (const float*)d_in[12];
    const float* oW1   = (const float*)d_in[13];
    const float* ob1   = (const float*)d_in[14];
    const float* oW2   = (const float*)d_in[15];
    const float* ob2   = (const float*)d_in[16];
    const float* oW3   = (const float*)d_in[17];
    const float* ob3   = (const float*)d_in[18];
    const float* oW4   = (const float*)d_in[19];
    const float* ob4   = (const float*)d_in[20];
    const float* fcW   = (const float*)d_in[21];
    const float* fcb   = (const float*)d_in[22];
    float* out = (float*)d_out;

    prep_kernel<<<768, 256>>>(gWih, gWhh, eW1, eW2, oW1, oW2, oW3, oW4);

    const int smem_bytes = 11 * 2048 * sizeof(float);   // 90112
    static int attr_done = 0;
    if (!attr_done) {
        cudaFuncSetAttribute(node_kernel, cudaFuncAttributeMaxDynamicSharedMemorySize, smem_bytes);
        attr_done = 1;
    }
    node_kernel<<<128, NTH, smem_bytes>>>(x, meta, eps, times, doses,
                                          gbih, gbhh, eb1, eb2,
                                          ob1, ob2, ob3, ob4, fcW, fcb, out);
}